// round 1
// baseline (speedup 1.0000x reference)
#include <cuda_runtime.h>

// Problem constants (fixed by the reference setup)
#define NL 50000      // n_links
#define NP 100000     // n_paths
#define ML 8          // max hops per path
#define D  64         // state dim (link == path)
#define G  192        // 3*D gate width

// ---------------- persistent device scratch (no allocs allowed) -------------
__device__ float g_link_state[NL * D];   // 12.8 MB
__device__ float g_path_state[NP * D];   // 25.6 MB
__device__ float g_GX[NL * G];           // 38.4 MB  (link_state @ Wx_p + b_p)
__device__ float g_M[NL * D];            // 12.8 MB  (segment_sum target)

// ---------------- math helpers ----------------------------------------------
__device__ __forceinline__ float sigm(float x) {
    return 1.0f / (1.0f + __expf(-x));
}
__device__ __forceinline__ float ftanh(float x) {
    x = fminf(15.0f, fmaxf(-15.0f, x));
    float e = __expf(2.0f * x);
    return (e - 1.0f) / (e + 1.0f);
}
__device__ __forceinline__ float selu(float x) {
    const float a = 1.6732632423543772f, s = 1.0507009873554805f;
    return x > 0.0f ? s * x : s * a * (__expf(x) - 1.0f);
}

// 4-row x JW-col register micro-tile GEMM over K=64, A from smem (scalar,
// broadcast across the 16 col-groups of a warp), W from smem as float4s.
template <int JW>
__device__ __forceinline__ void gemm_rows4(const float* __restrict__ sA, int lda, int row0,
                                           const float* __restrict__ sW, int ldw, int col0,
                                           float (&acc)[4][JW])
{
#pragma unroll 4
    for (int k = 0; k < 64; ++k) {
        float a[4];
#pragma unroll
        for (int i = 0; i < 4; ++i) a[i] = sA[(row0 + i) * lda + k];
#pragma unroll
        for (int j4 = 0; j4 < JW / 4; ++j4) {
            float4 w = *(const float4*)&sW[k * ldw + col0 + 4 * j4];
#pragma unroll
            for (int i = 0; i < 4; ++i) {
                acc[i][4 * j4 + 0] += a[i] * w.x;
                acc[i][4 * j4 + 1] += a[i] * w.y;
                acc[i][4 * j4 + 2] += a[i] * w.z;
                acc[i][4 * j4 + 3] += a[i] * w.w;
            }
        }
    }
}

// ---------------- kernel: init states ---------------------------------------
__global__ void k_init(const float* __restrict__ cap, const float* __restrict__ traf,
                       int n_links, int n_paths)
{
    int i = blockIdx.x * blockDim.x + threadIdx.x;
    int tot = (n_links + n_paths) * D;
    if (i >= tot) return;
    if (i < n_links * D) {
        int u = i & (D - 1);
        g_link_state[i] = (u == 0) ? cap[i >> 6] : 0.0f;
    } else {
        int j = i - n_links * D;
        int u = j & (D - 1);
        g_path_state[j] = (u == 0) ? traf[j >> 6] : 0.0f;
    }
}

__global__ void k_zeroM(int n)
{
    int i = blockIdx.x * blockDim.x + threadIdx.x;
    if (i < n) g_M[i] = 0.0f;
}

// ---------------- kernel: GX = link_state @ Wx_p + b_p ----------------------
// 128 links/block, 512 threads, 4x12 micro-tile.
__global__ void __launch_bounds__(512, 1)
k_gx(const float* __restrict__ W, const float* __restrict__ b, int n_links)
{
    extern __shared__ float sm[];
    float* sW = sm;                 // 64*192 = 12288
    float* sA = sW + 64 * G;        // 128*65 = 8320
    float* sb = sA + 128 * 65;      // 192
    int tid = threadIdx.x;
    int l0 = blockIdx.x * 128;

    for (int i = tid; i < 64 * G; i += 512) sW[i] = W[i];
    if (tid < G) sb[tid] = b[tid];
    for (int idx = tid; idx < 128 * D; idx += 512) {
        int r = idx >> 6, u = idx & 63;
        sA[r * 65 + u] = (l0 + r < n_links) ? g_link_state[(l0 + r) * D + u] : 0.0f;
    }
    __syncthreads();

    int pg = tid >> 4, cg = tid & 15;  // rows pg*4..+3, cols cg*12..+11
    float acc[4][12];
#pragma unroll
    for (int i = 0; i < 4; ++i)
#pragma unroll
        for (int j = 0; j < 12; ++j) acc[i][j] = 0.0f;

    gemm_rows4<12>(sA, 65, pg * 4, sW, G, cg * 12, acc);

#pragma unroll
    for (int i = 0; i < 4; ++i) {
        int gl = l0 + pg * 4 + i;
        if (gl < n_links) {
            float* dst = &g_GX[gl * G + cg * 12];
            float4 o0 = make_float4(acc[i][0] + sb[cg * 12 + 0], acc[i][1] + sb[cg * 12 + 1],
                                    acc[i][2] + sb[cg * 12 + 2], acc[i][3] + sb[cg * 12 + 3]);
            float4 o1 = make_float4(acc[i][4] + sb[cg * 12 + 4], acc[i][5] + sb[cg * 12 + 5],
                                    acc[i][6] + sb[cg * 12 + 6], acc[i][7] + sb[cg * 12 + 7]);
            float4 o2 = make_float4(acc[i][8] + sb[cg * 12 + 8], acc[i][9] + sb[cg * 12 + 9],
                                    acc[i][10] + sb[cg * 12 + 10], acc[i][11] + sb[cg * 12 + 11]);
            *(float4*)(dst + 0) = o0;
            *(float4*)(dst + 4) = o1;
            *(float4*)(dst + 8) = o2;
        }
    }
}

// ---------------- kernel: fused path GRU scan --------------------------------
// 128 paths/block resident in smem across all 8 steps. Per step:
//   GH = H @ Wh_p (reg-tiled GEMM into smem), then fused GRU elementwise with
//   gx gathered from GX[link], in-place H update, atomic scatter-add into M.
__global__ void __launch_bounds__(512, 1)
k_scan(const int* __restrict__ links, const float* __restrict__ Wh,
       int n_paths, int accumM)
{
    extern __shared__ float sm[];
    float* sW  = sm;                   // 12288
    float* sH  = sW + 64 * G;          // 128*65 = 8320   (H[p][u])
    float* sGH = sH + 128 * 65;        // 128*196 = 25088 (GH[p][j])
    int*   lnk = (int*)(sGH + 128 * 196); // 128 ints
    int tid = threadIdx.x;
    int p0 = blockIdx.x * 128;

    for (int i = tid; i < 64 * G; i += 512) sW[i] = Wh[i];
    for (int idx = tid; idx < 128 * D; idx += 512) {
        int p = idx >> 6, u = idx & 63;
        sH[p * 65 + u] = (p0 + p < n_paths) ? g_path_state[(p0 + p) * D + u] : 0.0f;
    }
    __syncthreads();

    int pg = tid >> 4, cg = tid & 15;

    for (int t = 0; t < ML; ++t) {
        // barrier: previous step's H updates complete before GEMM reads;
        // also makes lnk safe to overwrite.
        if (tid < 128) lnk[tid] = (p0 + tid < n_paths) ? links[(p0 + tid) * ML + t] : 0;

        float acc[4][12];
#pragma unroll
        for (int i = 0; i < 4; ++i)
#pragma unroll
            for (int j = 0; j < 12; ++j) acc[i][j] = 0.0f;

        gemm_rows4<12>(sH, 65, pg * 4, sW, G, cg * 12, acc);

#pragma unroll
        for (int i = 0; i < 4; ++i) {
            float* dst = &sGH[(pg * 4 + i) * 196 + cg * 12];
            *(float4*)(dst + 0) = make_float4(acc[i][0], acc[i][1], acc[i][2], acc[i][3]);
            *(float4*)(dst + 4) = make_float4(acc[i][4], acc[i][5], acc[i][6], acc[i][7]);
            *(float4*)(dst + 8) = make_float4(acc[i][8], acc[i][9], acc[i][10], acc[i][11]);
        }
        __syncthreads();  // GH + lnk ready; GEMM reads of sH complete

        for (int idx = tid; idx < 128 * D; idx += 512) {
            int p = idx >> 6, u = idx & 63;
            if (p0 + p < n_paths) {
                int ln = lnk[p];
                const float* gx = &g_GX[ln * G];
                const float* gh = &sGH[p * 196];
                float z  = sigm(gx[u] + gh[u]);
                float r  = sigm(gx[64 + u] + gh[64 + u]);
                float hc = ftanh(gx[128 + u] + r * gh[128 + u]);
                float h  = sH[p * 65 + u];
                float hn = z * h + (1.0f - z) * hc;
                sH[p * 65 + u] = hn;
                if (accumM) atomicAdd(&g_M[ln * D + u], hn);
            }
        }
        __syncthreads();  // H updates visible for next step's GEMM
    }

    for (int idx = tid; idx < 128 * D; idx += 512) {
        int p = idx >> 6, u = idx & 63;
        if (p0 + p < n_paths) g_path_state[(p0 + p) * D + u] = sH[p * 65 + u];
    }
}

// ---------------- kernel: link GRU -------------------------------------------
// link_state = GRU(x = M, h = link_state; Wx_e, Wh_e, b_e). 64 links/block.
__global__ void __launch_bounds__(256, 1)
k_lgru(const float* __restrict__ Wx, const float* __restrict__ Wh,
       const float* __restrict__ b, int n_links)
{
    extern __shared__ float sm[];
    float* sW  = sm;                 // 12288
    float* sM  = sW + 12288;         // 64*65 = 4160
    float* sLS = sM + 4160;          // 4160
    float* sGA = sLS + 4160;         // 64*196 = 12544  (x-gates + b)
    float* sGB = sGA + 12544;        // 12544           (h-gates)
    float* sb  = sGB + 12544;        // 192
    int tid = threadIdx.x;
    int l0 = blockIdx.x * 64;

    for (int i = tid; i < 12288; i += 256) sW[i] = Wx[i];
    if (tid < G) sb[tid] = b[tid];
    for (int idx = tid; idx < 64 * D; idx += 256) {
        int r = idx >> 6, u = idx & 63;
        bool v = (l0 + r < n_links);
        sM[r * 65 + u]  = v ? g_M[(l0 + r) * D + u] : 0.0f;
        sLS[r * 65 + u] = v ? g_link_state[(l0 + r) * D + u] : 0.0f;
    }
    __syncthreads();

    int pg = tid >> 4, cg = tid & 15;
    {
        float acc[4][12];
#pragma unroll
        for (int i = 0; i < 4; ++i)
#pragma unroll
            for (int j = 0; j < 12; ++j) acc[i][j] = 0.0f;
        gemm_rows4<12>(sM, 65, pg * 4, sW, G, cg * 12, acc);
#pragma unroll
        for (int i = 0; i < 4; ++i)
#pragma unroll
            for (int j = 0; j < 12; ++j)
                sGA[(pg * 4 + i) * 196 + cg * 12 + j] = acc[i][j] + sb[cg * 12 + j];
    }
    __syncthreads();
    for (int i = tid; i < 12288; i += 256) sW[i] = Wh[i];
    __syncthreads();
    {
        float acc[4][12];
#pragma unroll
        for (int i = 0; i < 4; ++i)
#pragma unroll
            for (int j = 0; j < 12; ++j) acc[i][j] = 0.0f;
        gemm_rows4<12>(sLS, 65, pg * 4, sW, G, cg * 12, acc);
#pragma unroll
        for (int i = 0; i < 4; ++i)
#pragma unroll
            for (int j = 0; j < 12; ++j)
                sGB[(pg * 4 + i) * 196 + cg * 12 + j] = acc[i][j];
    }
    __syncthreads();

    for (int idx = tid; idx < 64 * D; idx += 256) {
        int p = idx >> 6, u = idx & 63;
        if (l0 + p < n_links) {
            float z  = sigm(sGA[p * 196 + u] + sGB[p * 196 + u]);
            float r  = sigm(sGA[p * 196 + 64 + u] + sGB[p * 196 + 64 + u]);
            float hc = ftanh(sGA[p * 196 + 128 + u] + r * sGB[p * 196 + 128 + u]);
            float h  = sLS[p * 65 + u];
            g_link_state[(l0 + p) * D + u] = z * h + (1.0f - z) * hc;
        }
    }
}

// ---------------- kernel: fused readout --------------------------------------
// o = selu(selu(PS@W1+b1)@W2+b2) . Wf[0:256] + PS . Wf[256:320] + bf
__global__ void __launch_bounds__(256, 1)
k_read(const float* __restrict__ W1, const float* __restrict__ b1,
       const float* __restrict__ W2, const float* __restrict__ b2,
       const float* __restrict__ Wf, const float* __restrict__ bf,
       float* __restrict__ out, int n_paths)
{
    extern __shared__ float sm[];
    float* sPS = sm;              // 64*65 = 4160
    float* sB  = sPS + 4160;      // 64*260 = 16640 (W1, then W2 k-chunks)
    float* sR1 = sB + 16640;      // 64*260 = 16640
    float* sO  = sR1 + 16640;     // 64
    float* swf = sO + 64;         // 320
    int tid = threadIdx.x;
    int p0 = blockIdx.x * 64;

    for (int idx = tid; idx < 64 * D; idx += 256) {
        int p = idx >> 6, u = idx & 63;
        sPS[p * 65 + u] = (p0 + p < n_paths) ? g_path_state[(p0 + p) * D + u] : 0.0f;
    }
    for (int idx = tid; idx < 64 * 256; idx += 256) {
        int k = idx >> 8, j = idx & 255;
        sB[k * 260 + j] = W1[idx];
    }
    if (tid < 64) sO[tid] = 0.0f;
    for (int i = tid; i < 320; i += 256) swf[i] = Wf[i];
    __syncthreads();

    int pg = tid >> 4, cg = tid & 15;  // 4 paths x 16 cols

    float acc[4][16];
#pragma unroll
    for (int i = 0; i < 4; ++i)
#pragma unroll
        for (int j = 0; j < 16; ++j) acc[i][j] = 0.0f;
    gemm_rows4<16>(sPS, 65, pg * 4, sB, 260, cg * 16, acc);

#pragma unroll
    for (int i = 0; i < 4; ++i)
#pragma unroll
        for (int j = 0; j < 16; ++j)
            sR1[(pg * 4 + i) * 260 + cg * 16 + j] = selu(acc[i][j] + b1[cg * 16 + j]);
    __syncthreads();

    float acc2[4][16];
#pragma unroll
    for (int i = 0; i < 4; ++i)
#pragma unroll
        for (int j = 0; j < 16; ++j) acc2[i][j] = 0.0f;

    for (int kc = 0; kc < 4; ++kc) {
        for (int idx = tid; idx < 64 * 256; idx += 256) {
            int k = idx >> 8, j = idx & 255;
            sB[k * 260 + j] = W2[(kc * 64 + k) * 256 + j];
        }
        __syncthreads();
        gemm_rows4<16>(sR1 + kc * 64, 260, pg * 4, sB, 260, cg * 16, acc2);
        __syncthreads();
    }

    float part[4] = {0.0f, 0.0f, 0.0f, 0.0f};
#pragma unroll
    for (int i = 0; i < 4; ++i)
#pragma unroll
        for (int j = 0; j < 16; ++j) {
            float v = selu(acc2[i][j] + b2[cg * 16 + j]);
            part[i] += v * swf[cg * 16 + j];
        }
#pragma unroll
    for (int i = 0; i < 4; ++i) atomicAdd(&sO[pg * 4 + i], part[i]);
    __syncthreads();

    if (tid < 64) {
        int p = tid;
        if (p0 + p < n_paths) {
            float d = sO[p] + bf[0];
#pragma unroll 8
            for (int u = 0; u < 64; ++u) d += sPS[p * 65 + u] * swf[256 + u];
            out[p0 + p] = d;
        }
    }
}

// ---------------- host launcher ----------------------------------------------
extern "C" void kernel_launch(void* const* d_in, const int* in_sizes, int n_in,
                              void* d_out, int out_size)
{
    const float* cap  = (const float*)d_in[0];
    const float* traf = (const float*)d_in[1];
    const int*   links= (const int*)d_in[2];
    // d_in[3] = paths, d_in[4] = seqs : structurally e = p*ML + t, unused
    const float* Wx_p = (const float*)d_in[5];
    const float* Wh_p = (const float*)d_in[6];
    const float* b_p  = (const float*)d_in[7];
    const float* Wx_e = (const float*)d_in[8];
    const float* Wh_e = (const float*)d_in[9];
    const float* b_e  = (const float*)d_in[10];
    const float* W1   = (const float*)d_in[11];
    const float* b1   = (const float*)d_in[12];
    const float* W2   = (const float*)d_in[13];
    const float* b2   = (const float*)d_in[14];
    const float* Wf   = (const float*)d_in[15];
    const float* bf   = (const float*)d_in[16];

    int n_links = in_sizes[0];
    int n_paths = in_sizes[1];
    float* out = (float*)d_out;

    const int SM_GX   = (12288 + 128 * 65 + 192) * 4;
    const int SM_SCAN = (12288 + 128 * 65 + 128 * 196) * 4 + 128 * 4;
    const int SM_LGRU = (12288 + 4160 + 4160 + 12544 + 12544 + 192) * 4;
    const int SM_READ = (4160 + 16640 + 16640 + 64 + 320) * 4;

    static bool attrs_set = false;
    if (!attrs_set) {
        cudaFuncSetAttribute(k_gx,   cudaFuncAttributeMaxDynamicSharedMemorySize, SM_GX);
        cudaFuncSetAttribute(k_scan, cudaFuncAttributeMaxDynamicSharedMemorySize, SM_SCAN);
        cudaFuncSetAttribute(k_lgru, cudaFuncAttributeMaxDynamicSharedMemorySize, SM_LGRU);
        cudaFuncSetAttribute(k_read, cudaFuncAttributeMaxDynamicSharedMemorySize, SM_READ);
        attrs_set = true;
    }

    k_init<<<((n_links + n_paths) * D + 255) / 256, 256>>>(cap, traf, n_links, n_paths);

    for (int it = 0; it < 3; ++it) {
        bool last = (it == 2);
        if (!last)
            k_zeroM<<<(n_links * D + 255) / 256, 256>>>(n_links * D);
        k_gx<<<(n_links + 127) / 128, 512, SM_GX>>>(Wx_p, b_p, n_links);
        k_scan<<<(n_paths + 127) / 128, 512, SM_SCAN>>>(links, Wh_p, n_paths, last ? 0 : 1);
        if (!last)
            k_lgru<<<(n_links + 63) / 64, 256, SM_LGRU>>>(Wx_e, Wh_e, b_e, n_links);
    }

    k_read<<<(n_paths + 63) / 64, 256, SM_READ>>>(W1, b1, W2, b2, Wf, bf, out, n_paths);
}